// round 9
// baseline (speedup 1.0000x reference)
#include <cuda_runtime.h>
#include <cuda_bf16.h>
#include <cstdint>

// LocalWindowAttention3D: all-MMA bf16 m16n8k16 (3-term split), 512 thr/CTA.
// R8: one-time bf16 repack of Q/K/V into fragment-order smem; P stored
// pre-split in PV fragment order (re-permuted k). Attention = LDS + MMA only.

namespace {
constexpr int CDIM = 128;
constexpr int SDIM = 110592;      // 48^3
constexpr int NWIN = 1728;        // 12^3
constexpr int QTP  = 132;         // qT/kT fp32 token-major pitch
constexpr int VP   = 68;          // vcm fp32 channel-major pitch
constexpr int XP   = 72;          // xs gather pitch
// ---- smem plan (bytes) ----
// Area A (fp32 qkv, dead after repack):
constexpr int O_QT  = 0;          // 64*132*4  = 33792
constexpr int O_KT  = 33792;      // 33792
constexpr int O_VCM = 67584;      // 128*68*4  = 34816   -> A ends 102400
// Area B (bf16 frags, written in repack):
constexpr int O_QFH = 102400;     // 8*8*32 uint2 = 16384
constexpr int O_QFL = 118784;
constexpr int O_KFH = 135168;
constexpr int O_KFL = 151552;
constexpr int O_VFH = 167936;     // 16*8*32 u32 = 16384
constexpr int O_VFL = 184320;     //                     -> B ends 200704
// Aliases inside B (dead before repack):
constexpr int O_XS  = 102400;     // gather scratch 36864
constexpr int O_XBH = 139264;     // x-frags hi 16384
constexpr int O_XBL = 155648;     // x-frags lo 16384
// Aliases inside A (written during attention):
constexpr int O_PFH = 0;          // [2][8][8][32] u32 = 16384
constexpr int O_PFL = 16384;
constexpr int O_PS  = 32768;      // 1024
constexpr int O_OFH = 33792;      // out-frags hi 16384 (uint2 cells)
constexpr int O_OFL = 50176;      // out-frags lo 16384
constexpr int SMEM_BYTES = 200704;
}

// Weight fragment images: [ch(8)][wrb(4)][ks(8)][lane(32)] uint4 = a0..a3 bf16x2.
// ch 0..5 = Wqkv, k-map pairs (c0+t4, c0+t4+4), (c0+8+t4, c0+12+t4).
// ch 6..7 = Wout, k-map pairs (c0+2t4, c0+2t4+1), (c0+2t4+8, c0+2t4+9).
__device__ uint4 gWh[8 * 4 * 8 * 32];
__device__ uint4 gWl[8 * 4 * 8 * 32];

__device__ __forceinline__ void split2(float a, float b, uint32_t& hi, uint32_t& lo) {
    __nv_bfloat162 h = __floats2bfloat162_rn(a, b);
    const float ra = a - __low2float(h);
    const float rb = b - __high2float(h);
    __nv_bfloat162 l = __floats2bfloat162_rn(ra, rb);
    hi = *reinterpret_cast<uint32_t*>(&h);
    lo = *reinterpret_cast<uint32_t*>(&l);
}
__device__ __forceinline__ void mma_bf16(float* d, uint32_t a0, uint32_t a1, uint32_t a2,
                                         uint32_t a3, uint32_t b0, uint32_t b1) {
    asm volatile(
        "mma.sync.aligned.m16n8k16.row.col.f32.bf16.bf16.f32 "
        "{%0,%1,%2,%3}, {%4,%5,%6,%7}, {%8,%9}, {%0,%1,%2,%3};"
        : "+f"(d[0]), "+f"(d[1]), "+f"(d[2]), "+f"(d[3])
        : "r"(a0), "r"(a1), "r"(a2), "r"(a3), "r"(b0), "r"(b1));
}

__global__ void prep_weights(const float* __restrict__ Wqkv, const float* __restrict__ Wout) {
    const int idx = blockIdx.x * 256 + threadIdx.x;     // 8192 frags
    if (idx >= 8192) return;
    const int lane = idx & 31;
    const int ks   = (idx >> 5) & 7;
    const int wrb  = (idx >> 8) & 3;
    const int ch   = idx >> 10;
    const int g = lane >> 2, t4 = lane & 3;
    const int e0 = ch * 64 + wrb * 16 + g;
    const float* W0 = (ch < 6) ? (Wqkv + (size_t)e0 * CDIM) : (Wout + (size_t)(e0 - 384) * CDIM);
    const float* W8 = W0 + 8 * CDIM;
    const int c0 = ks * 16;
    int cs0, cs1, cs2, cs3;
    if (ch < 6) { cs0 = c0 + t4;     cs1 = c0 + t4 + 4;     cs2 = c0 + 8 + t4;      cs3 = c0 + 12 + t4; }
    else        { cs0 = c0 + t4 * 2; cs1 = c0 + t4 * 2 + 1; cs2 = c0 + t4 * 2 + 8;  cs3 = c0 + t4 * 2 + 9; }
    uint4 h, l;
    split2(W0[cs0], W0[cs1], h.x, l.x);
    split2(W8[cs0], W8[cs1], h.y, l.y);
    split2(W0[cs2], W0[cs3], h.z, l.z);
    split2(W8[cs2], W8[cs3], h.w, l.w);
    gWh[idx] = h;
    gWl[idx] = l;
}

// One 64(e) x 64(t) x 128(c) projection GEMM warp-tile.
__device__ __forceinline__ void gemm_chunk(int ch, int wrb, int nhalf, int lane,
                                           const uint2* __restrict__ bfh,
                                           const uint2* __restrict__ bfl,
                                           float (&d)[4][4])
{
    const uint4* ph = gWh + ((ch * 4 + wrb) * 8) * 32 + lane;
    const uint4* pl = gWl + ((ch * 4 + wrb) * 8) * 32 + lane;
    #pragma unroll
    for (int nt = 0; nt < 4; ++nt)
        #pragma unroll
        for (int j = 0; j < 4; ++j) d[nt][j] = 0.f;

    #pragma unroll
    for (int ks = 0; ks < 8; ++ks) {
        const uint4 ah = __ldg(ph + ks * 32);
        const uint4 al = __ldg(pl + ks * 32);
        #pragma unroll
        for (int nt = 0; nt < 4; ++nt) {
            const int cell = ((nhalf * 4 + nt) * 8 + ks) * 32 + lane;
            const uint2 bh = bfh[cell];
            const uint2 bl = bfl[cell];
            mma_bf16(d[nt], ah.x, ah.y, ah.z, ah.w, bh.x, bh.y);
            mma_bf16(d[nt], ah.x, ah.y, ah.z, ah.w, bl.x, bl.y);
            mma_bf16(d[nt], al.x, al.y, al.z, al.w, bh.x, bh.y);
        }
    }
}

__global__ __launch_bounds__(512, 1)
void lwa3d_mma(const float* __restrict__ x, const float* __restrict__ bout,
               float* __restrict__ out)
{
    extern __shared__ char smc[];
    float* qT  = reinterpret_cast<float*>(smc + O_QT);
    float* kT  = reinterpret_cast<float*>(smc + O_KT);
    float* vcm = reinterpret_cast<float*>(smc + O_VCM);
    float* xs  = reinterpret_cast<float*>(smc + O_XS);
    uint2* xbh = reinterpret_cast<uint2*>(smc + O_XBH);
    uint2* xbl = reinterpret_cast<uint2*>(smc + O_XBL);
    uint2* qfh = reinterpret_cast<uint2*>(smc + O_QFH);
    uint2* qfl = reinterpret_cast<uint2*>(smc + O_QFL);
    uint2* kfh = reinterpret_cast<uint2*>(smc + O_KFH);
    uint2* kfl = reinterpret_cast<uint2*>(smc + O_KFL);
    uint32_t* vfh = reinterpret_cast<uint32_t*>(smc + O_VFH);
    uint32_t* vfl = reinterpret_cast<uint32_t*>(smc + O_VFL);
    uint32_t* pfh0 = reinterpret_cast<uint32_t*>(smc + O_PFH);
    uint32_t* pfl0 = reinterpret_cast<uint32_t*>(smc + O_PFL);
    float* ps  = reinterpret_cast<float*>(smc + O_PS);
    uint32_t* ofhw = reinterpret_cast<uint32_t*>(smc + O_OFH);
    uint32_t* oflw = reinterpret_cast<uint32_t*>(smc + O_OFL);

    const int tid  = threadIdx.x;
    const int wid  = tid >> 5;
    const int lane = tid & 31;
    const int g    = lane >> 2;
    const int t4   = lane & 3;
    const int n = blockIdx.x;
    const int b = blockIdx.y;
    const float scale = 0.08838834764831845f;   // 128^-0.5

    // ---------- gather x window into xs [128c][64t] ----------
    {
        const int ndi = n / 144, nhi = (n / 12) % 12, nwi = n % 12;
        const float* xb = x + (size_t)b * CDIM * SDIM;
        const int sbase = ((ndi * 4) * 48 + nhi * 4) * 48 + nwi * 4;
        for (int i = tid; i < CDIM * 16; i += 512) {
            const int c = i >> 4;
            const int gg = i & 15;
            const int s0 = sbase + ((gg >> 2) * 48 + (gg & 3)) * 48;
            *reinterpret_cast<float4*>(xs + c * XP + gg * 4) =
                *reinterpret_cast<const float4*>(xb + (size_t)c * SDIM + s0);
        }
    }
    __syncthreads();

    // ---------- build bf16 hi/lo x B-fragments ----------
    for (int cell = tid; cell < 2048; cell += 512) {
        const int l2 = cell & 31;
        const int ks = (cell >> 5) & 7;
        const int tb = cell >> 8;
        const int t  = tb * 8 + (l2 >> 2);
        const int c0 = ks * 16 + (l2 & 3);
        uint32_t h0, l0, h1, l1;
        split2(xs[c0 * XP + t], xs[(c0 + 4) * XP + t], h0, l0);
        split2(xs[(c0 + 8) * XP + t], xs[(c0 + 12) * XP + t], h1, l1);
        xbh[cell] = make_uint2(h0, h1);
        xbl[cell] = make_uint2(l0, l1);
    }
    __syncthreads();

    // ---------- QKV = Wqkv @ x : 48 warp-tasks, 3 per warp ----------
    #pragma unroll 1
    for (int i = 0; i < 3; ++i) {
        const int task  = wid * 3 + i;
        const int ch    = task >> 3;
        const int wrb   = (task >> 1) & 3;
        const int nhalf = task & 1;
        float d[4][4];
        gemm_chunk(ch, wrb, nhalf, lane, xbh, xbl, d);
        const int e0 = (ch & 1) * 64 + wrb * 16 + g;
        const int t0 = nhalf * 32 + t4 * 2;
        if (ch < 2) {            // Q: pre-scaled token-major fp32
            #pragma unroll
            for (int nt = 0; nt < 4; ++nt) {
                const int t = t0 + nt * 8;
                qT[t * QTP + e0]           = d[nt][0] * scale;
                qT[(t + 1) * QTP + e0]     = d[nt][1] * scale;
                qT[t * QTP + e0 + 8]       = d[nt][2] * scale;
                qT[(t + 1) * QTP + e0 + 8] = d[nt][3] * scale;
            }
        } else if (ch < 4) {     // K: token-major fp32
            #pragma unroll
            for (int nt = 0; nt < 4; ++nt) {
                const int t = t0 + nt * 8;
                kT[t * QTP + e0]           = d[nt][0];
                kT[(t + 1) * QTP + e0]     = d[nt][1];
                kT[t * QTP + e0 + 8]       = d[nt][2];
                kT[(t + 1) * QTP + e0 + 8] = d[nt][3];
            }
        } else {                 // V: channel-major fp32
            float* v0 = vcm + e0 * VP + t0;
            float* v1 = v0 + 8 * VP;
            #pragma unroll
            for (int nt = 0; nt < 4; ++nt) {
                *reinterpret_cast<float2*>(v0 + nt * 8) = make_float2(d[nt][0], d[nt][1]);
                *reinterpret_cast<float2*>(v1 + nt * 8) = make_float2(d[nt][2], d[nt][3]);
            }
        }
    }
    __syncthreads();

    // ---------- repack Q,K,V -> bf16 hi/lo fragment arrays ----------
    // Q/K: cell [tb(8)][h(8)][lane]: token t=tb*8+g, pairs (h16+t4, +4) & (+8, +12)
    #pragma unroll 1
    for (int cell = tid; cell < 2048; cell += 512) {
        const int l2 = cell & 31;
        const int hh = (cell >> 5) & 7;
        const int tb = cell >> 8;
        const int t  = tb * 8 + (l2 >> 2);
        const int c0 = hh * 16 + (l2 & 3);
        uint32_t h0, l0, h1, l1;
        split2(qT[t * QTP + c0], qT[t * QTP + c0 + 4], h0, l0);
        split2(qT[t * QTP + c0 + 8], qT[t * QTP + c0 + 12], h1, l1);
        qfh[cell] = make_uint2(h0, h1);
        qfl[cell] = make_uint2(l0, l1);
        split2(kT[t * QTP + c0], kT[t * QTP + c0 + 4], h0, l0);
        split2(kT[t * QTP + c0 + 8], kT[t * QTP + c0 + 12], h1, l1);
        kfh[cell] = make_uint2(h0, h1);
        kfl[cell] = make_uint2(l0, l1);
    }
    // V: cell [cblk(16)][kb(8)][lane]: c=cblk*8+g, pair (kb*8+2t4, +1)
    #pragma unroll 1
    for (int cell = tid; cell < 4096; cell += 512) {
        const int l2 = cell & 31;
        const int kb = (cell >> 5) & 7;
        const int cb = cell >> 8;
        const int c  = cb * 8 + (l2 >> 2);
        const float2 v = *reinterpret_cast<const float2*>(vcm + c * VP + kb * 8 + (l2 & 3) * 2);
        uint32_t h0, l0;
        split2(v.x, v.y, h0, l0);
        vfh[cell] = h0;
        vfl[cell] = l0;
    }
    __syncthreads();

    // ---------- MMA attention: 2 heads in flight ----------
    const int hsel = wid >> 3;
    const int sub  = wid & 7;
    const int mb  = sub >> 1;           // QK: 16q row-block
    const int nh  = sub & 1;            // QK: 32k col-half
    const int mbp = sub & 3;            // PV: 16q row-block
    const int nhd = sub >> 2;           // PV: 8hd col-half
    uint32_t* pfh = pfh0 + hsel * 2048;
    uint32_t* pfl = pfl0 + hsel * 2048;
    float* psh = ps + hsel * 128;

    #pragma unroll 1
    for (int hh = 0; hh < 4; ++hh) {
        const int h = hh * 2 + hsel;

        // ---- S = Q K^T (scaled): fragment loads, 3-term bf16 ----
        float d[4][4];
        #pragma unroll
        for (int nt = 0; nt < 4; ++nt)
            #pragma unroll
            for (int j = 0; j < 4; ++j) d[nt][j] = 0.f;
        {
            const int ia0 = ((2 * mb) * 8 + h) * 32 + lane;
            const int ia1 = ((2 * mb + 1) * 8 + h) * 32 + lane;
            const uint2 Ah0 = qfh[ia0], Ah1 = qfh[ia1];
            const uint2 Al0 = qfl[ia0], Al1 = qfl[ia1];
            #pragma unroll
            for (int nt = 0; nt < 4; ++nt) {
                const int ib = ((nh * 4 + nt) * 8 + h) * 32 + lane;
                const uint2 Bh = kfh[ib];
                const uint2 Bl = kfl[ib];
                mma_bf16(d[nt], Ah0.x, Ah1.x, Ah0.y, Ah1.y, Bh.x, Bh.y);
                mma_bf16(d[nt], Ah0.x, Ah1.x, Ah0.y, Ah1.y, Bl.x, Bl.y);
                mma_bf16(d[nt], Al0.x, Al1.x, Al0.y, Al1.y, Bh.x, Bh.y);
            }
        }

        // ---- exp (unnormalized P) + row sums ----
        float e[4][4];
        float s0 = 0.f, s1 = 0.f;
        #pragma unroll
        for (int nt = 0; nt < 4; ++nt) {
            e[nt][0] = __expf(d[nt][0]);
            e[nt][1] = __expf(d[nt][1]);
            e[nt][2] = __expf(d[nt][2]);
            e[nt][3] = __expf(d[nt][3]);
            s0 += e[nt][0] + e[nt][1];
            s1 += e[nt][2] + e[nt][3];
        }
        s0 += __shfl_xor_sync(0xFFFFFFFF, s0, 1);
        s0 += __shfl_xor_sync(0xFFFFFFFF, s0, 2);
        s1 += __shfl_xor_sync(0xFFFFFFFF, s1, 1);
        s1 += __shfl_xor_sync(0xFFFFFFFF, s1, 2);
        if (t4 == 0) {
            psh[nh * 64 + mb * 16 + g]     = s0;
            psh[nh * 64 + mb * 16 + g + 8] = s1;
        }

        // ---- write P pre-split in PV fragment order ----
        // thread holds P[q=mb*16+g(+8)][kt=kb*8+2t4, +1], kb = nh*4+nt
        #pragma unroll
        for (int nt = 0; nt < 4; ++nt) {
            const int kb = nh * 4 + nt;
            uint32_t h0, l0, h1, l1;
            split2(e[nt][0], e[nt][1], h0, l0);
            split2(e[nt][2], e[nt][3], h1, l1);
            const int i0 = ((2 * mb) * 8 + kb) * 32 + lane;
            const int i1 = ((2 * mb + 1) * 8 + kb) * 32 + lane;
            pfh[i0] = h0; pfl[i0] = l0;
            pfh[i1] = h1; pfl[i1] = l1;
        }
        __syncthreads();

        // ---- O = P V : 4 k-steps (kb pairs), pure fragment loads ----
        float oa[4] = {0.f, 0.f, 0.f, 0.f};
        float ob[4] = {0.f, 0.f, 0.f, 0.f};
        const int cblk = 2 * h + nhd;
        #pragma unroll
        for (int ks = 0; ks < 4; ++ks) {
            const int ia0 = ((2 * mbp) * 8 + 2 * ks) * 32 + lane;
            const int ia1 = ((2 * mbp + 1) * 8 + 2 * ks) * 32 + lane;
            const uint32_t ph0 = pfh[ia0],      pl0 = pfl[ia0];
            const uint32_t ph1 = pfh[ia1],      pl1 = pfl[ia1];
            const uint32_t ph2 = pfh[ia0 + 32], pl2 = pfl[ia0 + 32];
            const uint32_t ph3 = pfh[ia1 + 32], pl3 = pfl[ia1 + 32];
            const int ib = (cblk * 8 + 2 * ks) * 32 + lane;
            const uint32_t vh0 = vfh[ib],      vl0 = vfl[ib];
            const uint32_t vh1 = vfh[ib + 32], vl1 = vfl[ib + 32];
            float* acc = (ks & 1) ? ob : oa;
            mma_bf16(acc, ph0, ph1, ph2, ph3, vh0, vh1);
            mma_bf16(acc, ph0, ph1, ph2, ph3, vl0, vl1);
            mma_bf16(acc, pl0, pl1, pl2, pl3, vh0, vh1);
        }
        #pragma unroll
        for (int j = 0; j < 4; ++j) oa[j] += ob[j];

        // ---- normalize + store as out-proj B fragments ----
        {
            const int q0r = mbp * 16 + g;
            const float r0 = 1.f / (psh[q0r] + psh[64 + q0r]);
            const float r1 = 1.f / (psh[q0r + 8] + psh[64 + q0r + 8]);
            uint32_t h0, l0, h1, l1;
            split2(oa[0] * r0, oa[1] * r0, h0, l0);
            split2(oa[2] * r1, oa[3] * r1, h1, l1);
            const int cellA = ((mbp * 2) * 8 + h) * 32 + lane;
            const int cellB = ((mbp * 2 + 1) * 8 + h) * 32 + lane;
            ofhw[cellA * 2 + nhd] = h0;
            oflw[cellA * 2 + nhd] = l0;
            ofhw[cellB * 2 + nhd] = h1;
            oflw[cellB * 2 + nhd] = l1;
        }
        __syncthreads();
    }

    // ---------- out = Wout @ ao + bout : 16 warp-tasks, 1 per warp ----------
    {
        const int ch    = 6 + (wid >> 3);
        const int wrb   = (wid >> 1) & 3;
        const int nhalf = wid & 1;
        float d[4][4];
        gemm_chunk(ch, wrb, nhalf, lane,
                   reinterpret_cast<const uint2*>(ofhw),
                   reinterpret_cast<const uint2*>(oflw), d);
        const int e0 = (ch - 6) * 64 + wrb * 16 + g;
        const float bb0 = __ldg(bout + e0);
        const float bb1 = __ldg(bout + e0 + 8);
        float* o0 = out + (size_t)b * CDIM * SDIM + (size_t)e0 * SDIM + n * 64 + nhalf * 32 + t4 * 2;
        float* o1 = o0 + (size_t)8 * SDIM;
        #pragma unroll
        for (int nt = 0; nt < 4; ++nt) {
            *reinterpret_cast<float2*>(o0 + nt * 8) = make_float2(d[nt][0] + bb0, d[nt][1] + bb0);
            *reinterpret_cast<float2*>(o1 + nt * 8) = make_float2(d[nt][2] + bb1, d[nt][3] + bb1);
        }
    }
}

extern "C" void kernel_launch(void* const* d_in, const int* in_sizes, int n_in,
                              void* d_out, int out_size)
{
    (void)in_sizes; (void)n_in; (void)out_size;
    const float* x    = (const float*)d_in[0];
    const float* Wqkv = (const float*)d_in[1];
    const float* Wout = (const float*)d_in[2];
    const float* bout = (const float*)d_in[3];
    float* out = (float*)d_out;

    prep_weights<<<32, 256>>>(Wqkv, Wout);

    cudaFuncSetAttribute(lwa3d_mma, cudaFuncAttributeMaxDynamicSharedMemorySize, SMEM_BYTES);
    dim3 grid(NWIN, 2);
    lwa3d_mma<<<grid, 512, SMEM_BYTES>>>(x, bout, out);
}

// round 10
// speedup vs baseline: 1.3842x; 1.3842x over previous
#include <cuda_runtime.h>
#include <cuda_bf16.h>
#include <cstdint>

// LocalWindowAttention3D: all-MMA bf16 m16n8k16 (3-term split), 512 thr/CTA.
// R10: register-resident P (QK D-frag == PV A-frag), Q/K/V stored directly
// as pre-split bf16 fragments from projection D-frags. 4 syncs total.

namespace {
constexpr int CDIM = 128;
constexpr int SDIM = 110592;      // 48^3
constexpr int NWIN = 1728;        // 12^3
constexpr int XP   = 72;          // xs gather pitch (floats)
// ---- smem plan (bytes) ----
constexpr int O_QFH = 0;          // 2048 uint2 = 16384
constexpr int O_QFL = 16384;
constexpr int O_KFH = 32768;
constexpr int O_KFL = 49152;      // -> 65536
constexpr int O_VFH = 65536;      // 16*264 u32 * 4 = 16896
constexpr int O_VFL = 82432;      // -> 99328
constexpr int O_OFH = 99328;      // 2048 uint2 = 16384
constexpr int O_OFL = 115712;     // -> 132096
// aliases (time-disjoint):
constexpr int O_XS  = 65536;      // gather scratch 36864 (dead before V/of writes)
constexpr int O_XBH = 102400;     // x frags hi 16384 (dead before of writes)
constexpr int O_XBL = 118784;     // x frags lo 16384 -> 135168
constexpr int SMEM_BYTES = 135168;
constexpr int VST = 264;          // vf cblk stride (u32), padded vs 256 -> no bank conflicts
}

// Weight fragment images: [ch(8)][wrb(4)][ks(8)][lane(32)] uint4 = a0..a3 bf16x2.
// ch 0..5 = Wqkv, k-map pairs (c0+t4, c0+t4+4), (c0+8+t4, c0+12+t4).
// ch 6..7 = Wout, k-map pairs (c0+2t4, c0+2t4+1), (c0+2t4+8, c0+2t4+9).
__device__ uint4 gWh[8 * 4 * 8 * 32];
__device__ uint4 gWl[8 * 4 * 8 * 32];

__device__ __forceinline__ void split2(float a, float b, uint32_t& hi, uint32_t& lo) {
    __nv_bfloat162 h = __floats2bfloat162_rn(a, b);
    const float ra = a - __low2float(h);
    const float rb = b - __high2float(h);
    __nv_bfloat162 l = __floats2bfloat162_rn(ra, rb);
    hi = *reinterpret_cast<uint32_t*>(&h);
    lo = *reinterpret_cast<uint32_t*>(&l);
}
__device__ __forceinline__ void mma_bf16(float* d, uint32_t a0, uint32_t a1, uint32_t a2,
                                         uint32_t a3, uint32_t b0, uint32_t b1) {
    asm volatile(
        "mma.sync.aligned.m16n8k16.row.col.f32.bf16.bf16.f32 "
        "{%0,%1,%2,%3}, {%4,%5,%6,%7}, {%8,%9}, {%0,%1,%2,%3};"
        : "+f"(d[0]), "+f"(d[1]), "+f"(d[2]), "+f"(d[3])
        : "r"(a0), "r"(a1), "r"(a2), "r"(a3), "r"(b0), "r"(b1));
}

__global__ void prep_weights(const float* __restrict__ Wqkv, const float* __restrict__ Wout) {
    const int idx = blockIdx.x * 256 + threadIdx.x;     // 8192 frags
    if (idx >= 8192) return;
    const int lane = idx & 31;
    const int ks   = (idx >> 5) & 7;
    const int wrb  = (idx >> 8) & 3;
    const int ch   = idx >> 10;
    const int g = lane >> 2, t4 = lane & 3;
    const int e0 = ch * 64 + wrb * 16 + g;
    const float* W0 = (ch < 6) ? (Wqkv + (size_t)e0 * CDIM) : (Wout + (size_t)(e0 - 384) * CDIM);
    const float* W8 = W0 + 8 * CDIM;
    const int c0 = ks * 16;
    int cs0, cs1, cs2, cs3;
    if (ch < 6) { cs0 = c0 + t4;     cs1 = c0 + t4 + 4;     cs2 = c0 + 8 + t4;      cs3 = c0 + 12 + t4; }
    else        { cs0 = c0 + t4 * 2; cs1 = c0 + t4 * 2 + 1; cs2 = c0 + t4 * 2 + 8;  cs3 = c0 + t4 * 2 + 9; }
    uint4 h, l;
    split2(W0[cs0], W0[cs1], h.x, l.x);
    split2(W8[cs0], W8[cs1], h.y, l.y);
    split2(W0[cs2], W0[cs3], h.z, l.z);
    split2(W8[cs2], W8[cs3], h.w, l.w);
    gWh[idx] = h;
    gWl[idx] = l;
}

// One 64(e) x 64(t) x 128(c) projection GEMM warp-tile.
__device__ __forceinline__ void gemm_chunk(int ch, int wrb, int nhalf, int lane,
                                           const uint2* __restrict__ bfh,
                                           const uint2* __restrict__ bfl,
                                           float (&d)[4][4])
{
    const uint4* ph = gWh + ((ch * 4 + wrb) * 8) * 32 + lane;
    const uint4* pl = gWl + ((ch * 4 + wrb) * 8) * 32 + lane;
    #pragma unroll
    for (int nt = 0; nt < 4; ++nt)
        #pragma unroll
        for (int j = 0; j < 4; ++j) d[nt][j] = 0.f;

    #pragma unroll
    for (int ks = 0; ks < 8; ++ks) {
        const uint4 ah = __ldg(ph + ks * 32);
        const uint4 al = __ldg(pl + ks * 32);
        #pragma unroll
        for (int nt = 0; nt < 4; ++nt) {
            const int cell = ((nhalf * 4 + nt) * 8 + ks) * 32 + lane;
            const uint2 bh = bfh[cell];
            const uint2 bl = bfl[cell];
            mma_bf16(d[nt], ah.x, ah.y, ah.z, ah.w, bh.x, bh.y);
            mma_bf16(d[nt], ah.x, ah.y, ah.z, ah.w, bl.x, bl.y);
            mma_bf16(d[nt], al.x, al.y, al.z, al.w, bh.x, bh.y);
        }
    }
}

__global__ __launch_bounds__(512, 1)
void lwa3d_mma(const float* __restrict__ x, const float* __restrict__ bout,
               float* __restrict__ out)
{
    extern __shared__ char smc[];
    uint2* qfh = reinterpret_cast<uint2*>(smc + O_QFH);
    uint2* qfl = reinterpret_cast<uint2*>(smc + O_QFL);
    uint2* kfh = reinterpret_cast<uint2*>(smc + O_KFH);
    uint2* kfl = reinterpret_cast<uint2*>(smc + O_KFL);
    uint32_t* qfhw = reinterpret_cast<uint32_t*>(smc + O_QFH);
    uint32_t* qflw = reinterpret_cast<uint32_t*>(smc + O_QFL);
    uint32_t* kfhw = reinterpret_cast<uint32_t*>(smc + O_KFH);
    uint32_t* kflw = reinterpret_cast<uint32_t*>(smc + O_KFL);
    uint32_t* vfh = reinterpret_cast<uint32_t*>(smc + O_VFH);
    uint32_t* vfl = reinterpret_cast<uint32_t*>(smc + O_VFL);
    uint2* ofh = reinterpret_cast<uint2*>(smc + O_OFH);
    uint2* ofl = reinterpret_cast<uint2*>(smc + O_OFL);
    float* xs  = reinterpret_cast<float*>(smc + O_XS);
    uint2* xbh = reinterpret_cast<uint2*>(smc + O_XBH);
    uint2* xbl = reinterpret_cast<uint2*>(smc + O_XBL);

    const int tid  = threadIdx.x;
    const int wid  = tid >> 5;
    const int lane = tid & 31;
    const int g    = lane >> 2;
    const int t4   = lane & 3;
    const int n = blockIdx.x;
    const int b = blockIdx.y;
    const float scale = 0.08838834764831845f;   // 128^-0.5

    // ---------- gather x window into xs [128c][64t] ----------
    {
        const int ndi = n / 144, nhi = (n / 12) % 12, nwi = n % 12;
        const float* xb = x + (size_t)b * CDIM * SDIM;
        const int sbase = ((ndi * 4) * 48 + nhi * 4) * 48 + nwi * 4;
        for (int i = tid; i < CDIM * 16; i += 512) {
            const int c = i >> 4;
            const int gg = i & 15;
            const int s0 = sbase + ((gg >> 2) * 48 + (gg & 3)) * 48;
            *reinterpret_cast<float4*>(xs + c * XP + gg * 4) =
                *reinterpret_cast<const float4*>(xb + (size_t)c * SDIM + s0);
        }
    }
    __syncthreads();

    // ---------- build bf16 hi/lo x B-fragments ----------
    for (int cell = tid; cell < 2048; cell += 512) {
        const int l2 = cell & 31;
        const int ks = (cell >> 5) & 7;
        const int tb = cell >> 8;
        const int t  = tb * 8 + (l2 >> 2);
        const int c0 = ks * 16 + (l2 & 3);
        uint32_t h0, l0, h1, l1;
        split2(xs[c0 * XP + t], xs[(c0 + 4) * XP + t], h0, l0);
        split2(xs[(c0 + 8) * XP + t], xs[(c0 + 12) * XP + t], h1, l1);
        xbh[cell] = make_uint2(h0, h1);
        xbl[cell] = make_uint2(l0, l1);
    }
    __syncthreads();

    // ---------- QKV = Wqkv @ x : 48 warp-tasks, 3 per warp ----------
    // Epilogues store Q/K/V directly as pre-split bf16 fragments.
    #pragma unroll 1
    for (int i = 0; i < 3; ++i) {
        const int task  = wid * 3 + i;
        const int ch    = task >> 3;
        const int wrb   = (task >> 1) & 3;
        const int nhalf = task & 1;
        float d[4][4];
        gemm_chunk(ch, wrb, nhalf, lane, xbh, xbl, d);

        if (ch < 4) {
            // Q/K: channel pair (e0, e0+8) within head h; k-map pairs (h16+m, h16+m+8)
            const int h = (ch & 1) * 4 + wrb;       // head (g<8 always)
            uint32_t* fh = (ch < 2) ? qfhw : kfhw;
            uint32_t* fl = (ch < 2) ? qflw : kflw;
            const float sc = (ch < 2) ? scale : 1.f;
            #pragma unroll
            for (int nt = 0; nt < 4; ++nt) {
                const int tb = nhalf * 4 + nt;
                uint32_t hh0, ll0, hh1, ll1;
                split2(d[nt][0] * sc, d[nt][2] * sc, hh0, ll0);   // token t (even)
                split2(d[nt][1] * sc, d[nt][3] * sc, hh1, ll1);   // token t+1
                const int base = (tb * 8 + h) * 32 + (g & 3);
                const int i0 = ((base + (2 * t4) * 4) << 1) | (g >> 2);
                const int i1 = ((base + (2 * t4 + 1) * 4) << 1) | (g >> 2);
                fh[i0] = hh0; fl[i0] = ll0;
                fh[i1] = hh1; fl[i1] = ll1;
            }
        } else {
            // V: channels e0, e0+8; token pairs (t, t+1) -> vf[cblk][kb][lane2]
            const int cb0 = (ch & 1) * 8 + wrb * 2;
            const int lane2 = g * 4 + t4;
            #pragma unroll
            for (int nt = 0; nt < 4; ++nt) {
                const int kb = nhalf * 4 + nt;
                uint32_t h0, l0, h1, l1;
                split2(d[nt][0], d[nt][1], h0, l0);
                split2(d[nt][2], d[nt][3], h1, l1);
                vfh[cb0 * VST + kb * 32 + lane2] = h0;
                vfl[cb0 * VST + kb * 32 + lane2] = l0;
                vfh[(cb0 + 1) * VST + kb * 32 + lane2] = h1;
                vfl[(cb0 + 1) * VST + kb * 32 + lane2] = l1;
            }
        }
    }
    __syncthreads();

    // ---------- attention: 32 tasks (8 heads x 4 q-blocks), 2 per warp, NO syncs ----------
    #pragma unroll 1
    for (int ti = 0; ti < 2; ++ti) {
        const int task = wid + ti * 16;
        const int h  = task >> 2;
        const int mb = task & 3;

        // ---- QK: A from qf, B from kf; P kept in registers ----
        const int cA = (2 * mb * 8 + h) * 32 + lane;
        const uint2 Ah0 = qfh[cA], Ah1 = qfh[cA + 256];
        const uint2 Al0 = qfl[cA], Al1 = qfl[cA + 256];

        uint32_t eh[8][2], el[8][2];
        float s0 = 0.f, s1 = 0.f;
        #pragma unroll
        for (int nh = 0; nh < 2; ++nh) {
            #pragma unroll
            for (int nt = 0; nt < 4; ++nt) {
                const int kb = nh * 4 + nt;
                const int cB = (kb * 8 + h) * 32 + lane;
                const uint2 Bh = kfh[cB];
                const uint2 Bl = kfl[cB];
                float d[4] = {0.f, 0.f, 0.f, 0.f};
                mma_bf16(d, Ah0.x, Ah1.x, Ah0.y, Ah1.y, Bh.x, Bh.y);
                mma_bf16(d, Ah0.x, Ah1.x, Ah0.y, Ah1.y, Bl.x, Bl.y);
                mma_bf16(d, Al0.x, Al1.x, Al0.y, Al1.y, Bh.x, Bh.y);
                const float e0 = __expf(d[0]);
                const float e1 = __expf(d[1]);
                const float e2 = __expf(d[2]);
                const float e3 = __expf(d[3]);
                s0 += e0 + e1;
                s1 += e2 + e3;
                split2(e0, e1, eh[kb][0], el[kb][0]);   // row q   pair (kt, kt+1)
                split2(e2, e3, eh[kb][1], el[kb][1]);   // row q+8
            }
        }
        s0 += __shfl_xor_sync(0xFFFFFFFF, s0, 1);
        s0 += __shfl_xor_sync(0xFFFFFFFF, s0, 2);
        s1 += __shfl_xor_sync(0xFFFFFFFF, s1, 1);
        s1 += __shfl_xor_sync(0xFFFFFFFF, s1, 2);

        // ---- PV: A = register P frags, B = vf; both 8-col halves (nb0/nb1) ----
        float oA[4] = {0.f, 0.f, 0.f, 0.f};
        float oB[4] = {0.f, 0.f, 0.f, 0.f};
        #pragma unroll
        for (int ks = 0; ks < 4; ++ks) {
            const uint32_t a0 = eh[2 * ks][0], a1 = eh[2 * ks][1];
            const uint32_t a2 = eh[2 * ks + 1][0], a3 = eh[2 * ks + 1][1];
            const uint32_t la0 = el[2 * ks][0], la1 = el[2 * ks][1];
            const uint32_t la2 = el[2 * ks + 1][0], la3 = el[2 * ks + 1][1];
            const int ib = (2 * h) * VST + (2 * ks) * 32 + lane;
            const uint32_t vh0 = vfh[ib],          vh1 = vfh[ib + 32];
            const uint32_t vl0 = vfl[ib],          vl1 = vfl[ib + 32];
            const uint32_t wh0 = vfh[ib + VST],    wh1 = vfh[ib + VST + 32];
            const uint32_t wl0 = vfl[ib + VST],    wl1 = vfl[ib + VST + 32];
            mma_bf16(oA, a0, a1, a2, a3, vh0, vh1);
            mma_bf16(oA, a0, a1, a2, a3, vl0, vl1);
            mma_bf16(oA, la0, la1, la2, la3, vh0, vh1);
            mma_bf16(oB, a0, a1, a2, a3, wh0, wh1);
            mma_bf16(oB, a0, a1, a2, a3, wl0, wl1);
            mma_bf16(oB, la0, la1, la2, la3, wh0, wh1);
        }

        // ---- normalize + store as out-proj B fragments (uint2 = nb0,nb1) ----
        const float r0 = 1.f / s0;
        const float r1 = 1.f / s1;
        uint32_t hx0, lx0, hy0, ly0, hx1, lx1, hy1, ly1;
        split2(oA[0] * r0, oA[1] * r0, hx0, lx0);   // row q,   nb0
        split2(oB[0] * r0, oB[1] * r0, hy0, ly0);   // row q,   nb1
        split2(oA[2] * r1, oA[3] * r1, hx1, lx1);   // row q+8, nb0
        split2(oB[2] * r1, oB[3] * r1, hy1, ly1);   // row q+8, nb1
        ofh[cA]       = make_uint2(hx0, hy0);
        ofl[cA]       = make_uint2(lx0, ly0);
        ofh[cA + 256] = make_uint2(hx1, hy1);
        ofl[cA + 256] = make_uint2(lx1, ly1);
    }
    __syncthreads();

    // ---------- out = Wout @ ao + bout : 16 warp-tasks, 1 per warp ----------
    {
        const int ch    = 6 + (wid >> 3);
        const int wrb   = (wid >> 1) & 3;
        const int nhalf = wid & 1;
        float d[4][4];
        gemm_chunk(ch, wrb, nhalf, lane, ofh, ofl, d);
        const int e0 = (ch - 6) * 64 + wrb * 16 + g;
        const float bb0 = __ldg(bout + e0);
        const float bb1 = __ldg(bout + e0 + 8);
        float* o0 = out + (size_t)b * CDIM * SDIM + (size_t)e0 * SDIM + n * 64 + nhalf * 32 + t4 * 2;
        float* o1 = o0 + (size_t)8 * SDIM;
        #pragma unroll
        for (int nt = 0; nt < 4; ++nt) {
            *reinterpret_cast<float2*>(o0 + nt * 8) = make_float2(d[nt][0] + bb0, d[nt][1] + bb0);
            *reinterpret_cast<float2*>(o1 + nt * 8) = make_float2(d[nt][2] + bb1, d[nt][3] + bb1);
        }
    }
}

extern "C" void kernel_launch(void* const* d_in, const int* in_sizes, int n_in,
                              void* d_out, int out_size)
{
    (void)in_sizes; (void)n_in; (void)out_size;
    const float* x    = (const float*)d_in[0];
    const float* Wqkv = (const float*)d_in[1];
    const float* Wout = (const float*)d_in[2];
    const float* bout = (const float*)d_in[3];
    float* out = (float*)d_out;

    prep_weights<<<32, 256>>>(Wqkv, Wout);

    cudaFuncSetAttribute(lwa3d_mma, cudaFuncAttributeMaxDynamicSharedMemorySize, SMEM_BYTES);
    dim3 grid(NWIN, 2);
    lwa3d_mma<<<grid, 512, SMEM_BYTES>>>(x, bout, out);
}

// round 11
// speedup vs baseline: 1.4725x; 1.0638x over previous
#include <cuda_runtime.h>
#include <cuda_bf16.h>
#include <cuda_fp16.h>
#include <cstdint>

// LocalWindowAttention3D R11: bf16 3-term for QKV/QK, fp16 2-term for PV and
// out-proj (P and O single-term fp16). Packed hi/lo smem fragments.
// 512 thr/CTA, 1 CTA/SM, 4 syncs.

namespace {
constexpr int CDIM = 128;
constexpr int SDIM = 110592;      // 48^3
constexpr int NWIN = 1728;        // 12^3
constexpr int XP   = 72;          // xs gather pitch (floats)
// ---- smem plan (bytes) ----
constexpr int O_QFH = 0;          // 2048 uint2 = 16384
constexpr int O_QFL = 16384;
constexpr int O_KFH = 32768;
constexpr int O_KFL = 49152;      // -> 65536
constexpr int O_VF  = 65536;      // uint2[16*264] = 33792 -> 99328
constexpr int O_OF  = 99328;      // uint2[2048] = 16384 -> 115712
// aliases (time-disjoint):
constexpr int O_XS  = 65536;      // gather scratch 36864 -> 102400 (dead before vf/of writes? xs
                                  // coexists with nothing: vf written in QKV after xs dead)
constexpr int O_XB  = 102400;     // x frags uint4[2048] = 32768 -> 135168 (dead before of reads)
constexpr int SMEM_BYTES = 135168;
constexpr int VST = 264;          // vf cblk stride in uint2 cells
}

// Weight fragment images: [ch(8)][wrb(4)][ks(8)][lane(32)] uint4.
// ch 0..5 = Wqkv bf16x2 pairs (c0+t4, c0+t4+4), (c0+8+t4, c0+12+t4).
// ch 6..7 = Wout fp16x2 pairs (c0+2t4, +1), (c0+2t4+8, +9).
__device__ uint4 gWh[8 * 4 * 8 * 32];
__device__ uint4 gWl[8 * 4 * 8 * 32];

__device__ __forceinline__ void split2(float a, float b, uint32_t& hi, uint32_t& lo) {
    __nv_bfloat162 h = __floats2bfloat162_rn(a, b);
    const float ra = a - __low2float(h);
    const float rb = b - __high2float(h);
    __nv_bfloat162 l = __floats2bfloat162_rn(ra, rb);
    hi = *reinterpret_cast<uint32_t*>(&h);
    lo = *reinterpret_cast<uint32_t*>(&l);
}
__device__ __forceinline__ void split2h(float a, float b, uint32_t& hi, uint32_t& lo) {
    __half2 h = __floats2half2_rn(a, b);
    const float ra = a - __half2float(__low2half(h));
    const float rb = b - __half2float(__high2half(h));
    __half2 l = __floats2half2_rn(ra, rb);
    hi = *reinterpret_cast<uint32_t*>(&h);
    lo = *reinterpret_cast<uint32_t*>(&l);
}
__device__ __forceinline__ uint32_t packh(float a, float b) {
    __half2 h = __floats2half2_rn(a, b);
    return *reinterpret_cast<uint32_t*>(&h);
}
__device__ __forceinline__ void mma_bf16(float* d, uint32_t a0, uint32_t a1, uint32_t a2,
                                         uint32_t a3, uint32_t b0, uint32_t b1) {
    asm volatile(
        "mma.sync.aligned.m16n8k16.row.col.f32.bf16.bf16.f32 "
        "{%0,%1,%2,%3}, {%4,%5,%6,%7}, {%8,%9}, {%0,%1,%2,%3};"
        : "+f"(d[0]), "+f"(d[1]), "+f"(d[2]), "+f"(d[3])
        : "r"(a0), "r"(a1), "r"(a2), "r"(a3), "r"(b0), "r"(b1));
}
__device__ __forceinline__ void mma_f16(float* d, uint32_t a0, uint32_t a1, uint32_t a2,
                                        uint32_t a3, uint32_t b0, uint32_t b1) {
    asm volatile(
        "mma.sync.aligned.m16n8k16.row.col.f32.f16.f16.f32 "
        "{%0,%1,%2,%3}, {%4,%5,%6,%7}, {%8,%9}, {%0,%1,%2,%3};"
        : "+f"(d[0]), "+f"(d[1]), "+f"(d[2]), "+f"(d[3])
        : "r"(a0), "r"(a1), "r"(a2), "r"(a3), "r"(b0), "r"(b1));
}

__global__ void prep_weights(const float* __restrict__ Wqkv, const float* __restrict__ Wout) {
    const int idx = blockIdx.x * 256 + threadIdx.x;     // 8192 frags
    if (idx >= 8192) return;
    const int lane = idx & 31;
    const int ks   = (idx >> 5) & 7;
    const int wrb  = (idx >> 8) & 3;
    const int ch   = idx >> 10;
    const int g = lane >> 2, t4 = lane & 3;
    const int e0 = ch * 64 + wrb * 16 + g;
    const float* W0 = (ch < 6) ? (Wqkv + (size_t)e0 * CDIM) : (Wout + (size_t)(e0 - 384) * CDIM);
    const float* W8 = W0 + 8 * CDIM;
    const int c0 = ks * 16;
    uint4 h, l;
    if (ch < 6) {
        const int cs0 = c0 + t4, cs1 = c0 + t4 + 4, cs2 = c0 + 8 + t4, cs3 = c0 + 12 + t4;
        split2(W0[cs0], W0[cs1], h.x, l.x);
        split2(W8[cs0], W8[cs1], h.y, l.y);
        split2(W0[cs2], W0[cs3], h.z, l.z);
        split2(W8[cs2], W8[cs3], h.w, l.w);
    } else {
        const int cs0 = c0 + t4 * 2, cs1 = cs0 + 1, cs2 = cs0 + 8, cs3 = cs0 + 9;
        split2h(W0[cs0], W0[cs1], h.x, l.x);
        split2h(W8[cs0], W8[cs1], h.y, l.y);
        split2h(W0[cs2], W0[cs3], h.z, l.z);
        split2h(W8[cs2], W8[cs3], h.w, l.w);
    }
    gWh[idx] = h;
    gWl[idx] = l;
}

// One 64(e) x 64(t) x 128(c) QKV GEMM warp-tile (bf16 3-term, packed B).
__device__ __forceinline__ void gemm_qkv(int ch, int wrb, int nhalf, int lane,
                                         const uint4* __restrict__ xbp,
                                         float (&d)[4][4])
{
    const uint4* ph = gWh + ((ch * 4 + wrb) * 8) * 32 + lane;
    const uint4* pl = gWl + ((ch * 4 + wrb) * 8) * 32 + lane;
    #pragma unroll
    for (int nt = 0; nt < 4; ++nt)
        #pragma unroll
        for (int j = 0; j < 4; ++j) d[nt][j] = 0.f;

    #pragma unroll
    for (int ks = 0; ks < 8; ++ks) {
        const uint4 ah = __ldg(ph + ks * 32);
        const uint4 al = __ldg(pl + ks * 32);
        #pragma unroll
        for (int nt = 0; nt < 4; ++nt) {
            const uint4 bb = xbp[((nhalf * 4 + nt) * 8 + ks) * 32 + lane];
            mma_bf16(d[nt], ah.x, ah.y, ah.z, ah.w, bb.x, bb.y);
            mma_bf16(d[nt], ah.x, ah.y, ah.z, ah.w, bb.z, bb.w);
            mma_bf16(d[nt], al.x, al.y, al.z, al.w, bb.x, bb.y);
        }
    }
}

__global__ __launch_bounds__(512, 1)
void lwa3d_mma(const float* __restrict__ x, const float* __restrict__ bout,
               float* __restrict__ out)
{
    extern __shared__ char smc[];
    uint2* qfh = reinterpret_cast<uint2*>(smc + O_QFH);
    uint2* qfl = reinterpret_cast<uint2*>(smc + O_QFL);
    uint2* kfh = reinterpret_cast<uint2*>(smc + O_KFH);
    uint2* kfl = reinterpret_cast<uint2*>(smc + O_KFL);
    uint32_t* qfhw = reinterpret_cast<uint32_t*>(smc + O_QFH);
    uint32_t* qflw = reinterpret_cast<uint32_t*>(smc + O_QFL);
    uint32_t* kfhw = reinterpret_cast<uint32_t*>(smc + O_KFH);
    uint32_t* kflw = reinterpret_cast<uint32_t*>(smc + O_KFL);
    uint2* vfp = reinterpret_cast<uint2*>(smc + O_VF);
    uint2* ofp = reinterpret_cast<uint2*>(smc + O_OF);
    float* xs  = reinterpret_cast<float*>(smc + O_XS);
    uint4* xbp = reinterpret_cast<uint4*>(smc + O_XB);

    const int tid  = threadIdx.x;
    const int wid  = tid >> 5;
    const int lane = tid & 31;
    const int g    = lane >> 2;
    const int t4   = lane & 3;
    const int n = blockIdx.x;
    const int b = blockIdx.y;
    const float scale = 0.08838834764831845f;   // 128^-0.5

    // ---------- gather x window into xs [128c][64t] ----------
    {
        const int ndi = n / 144, nhi = (n / 12) % 12, nwi = n % 12;
        const float* xb = x + (size_t)b * CDIM * SDIM;
        const int sbase = ((ndi * 4) * 48 + nhi * 4) * 48 + nwi * 4;
        for (int i = tid; i < CDIM * 16; i += 512) {
            const int c = i >> 4;
            const int gg = i & 15;
            const int s0 = sbase + ((gg >> 2) * 48 + (gg & 3)) * 48;
            *reinterpret_cast<float4*>(xs + c * XP + gg * 4) =
                *reinterpret_cast<const float4*>(xb + (size_t)c * SDIM + s0);
        }
    }
    __syncthreads();

    // ---------- build packed bf16 hi/lo x B-fragments ----------
    for (int cell = tid; cell < 2048; cell += 512) {
        const int l2 = cell & 31;
        const int ks = (cell >> 5) & 7;
        const int tb = cell >> 8;
        const int t  = tb * 8 + (l2 >> 2);
        const int c0 = ks * 16 + (l2 & 3);
        uint32_t h0, l0, h1, l1;
        split2(xs[c0 * XP + t], xs[(c0 + 4) * XP + t], h0, l0);
        split2(xs[(c0 + 8) * XP + t], xs[(c0 + 12) * XP + t], h1, l1);
        xbp[cell] = make_uint4(h0, h1, l0, l1);
    }
    __syncthreads();

    // ---------- QKV = Wqkv @ x : 48 warp-tasks, 3 per warp ----------
    #pragma unroll 1
    for (int i = 0; i < 3; ++i) {
        const int task  = wid * 3 + i;
        const int ch    = task >> 3;
        const int wrb   = (task >> 1) & 3;
        const int nhalf = task & 1;
        float d[4][4];
        gemm_qkv(ch, wrb, nhalf, lane, xbp, d);

        if (ch < 4) {
            // Q/K: channel pair (e0, e0+8) within head h; k-map pairs (h16+m, h16+m+8)
            const int h = (ch & 1) * 4 + wrb;
            uint32_t* fh = (ch < 2) ? qfhw : kfhw;
            uint32_t* fl = (ch < 2) ? qflw : kflw;
            const float sc = (ch < 2) ? scale : 1.f;
            #pragma unroll
            for (int nt = 0; nt < 4; ++nt) {
                const int tb = nhalf * 4 + nt;
                uint32_t hh0, ll0, hh1, ll1;
                split2(d[nt][0] * sc, d[nt][2] * sc, hh0, ll0);   // token t (even)
                split2(d[nt][1] * sc, d[nt][3] * sc, hh1, ll1);   // token t+1
                const int base = (tb * 8 + h) * 32 + (g & 3);
                const int i0 = ((base + (2 * t4) * 4) << 1) | (g >> 2);
                const int i1 = ((base + (2 * t4 + 1) * 4) << 1) | (g >> 2);
                fh[i0] = hh0; fl[i0] = ll0;
                fh[i1] = hh1; fl[i1] = ll1;
            }
        } else {
            // V: fp16 2-term, channels e0, e0+8; vf[cblk][kb][lane2] = {h,l}
            const int cb0 = (ch & 1) * 8 + wrb * 2;
            const int lane2 = g * 4 + t4;
            #pragma unroll
            for (int nt = 0; nt < 4; ++nt) {
                const int kb = nhalf * 4 + nt;
                uint32_t h0, l0, h1, l1;
                split2h(d[nt][0], d[nt][1], h0, l0);
                split2h(d[nt][2], d[nt][3], h1, l1);
                vfp[cb0 * VST + kb * 32 + lane2] = make_uint2(h0, l0);
                vfp[(cb0 + 1) * VST + kb * 32 + lane2] = make_uint2(h1, l1);
            }
        }
    }
    __syncthreads();

    // ---------- attention: 32 tasks (8 heads x 4 q-blocks), 2 per warp ----------
    #pragma unroll 1
    for (int ti = 0; ti < 2; ++ti) {
        const int task = wid + ti * 16;
        const int h  = task >> 2;
        const int mb = task & 3;

        // ---- QK (bf16 3-term): P kept in registers as fp16 ----
        const int cA = (2 * mb * 8 + h) * 32 + lane;
        const uint2 Ah0 = qfh[cA], Ah1 = qfh[cA + 256];
        const uint2 Al0 = qfl[cA], Al1 = qfl[cA + 256];

        uint32_t ep[8][2];
        float s0 = 0.f, s1 = 0.f;
        #pragma unroll
        for (int nh = 0; nh < 2; ++nh) {
            #pragma unroll
            for (int nt = 0; nt < 4; ++nt) {
                const int kb = nh * 4 + nt;
                const int cB = (kb * 8 + h) * 32 + lane;
                const uint2 Bh = kfh[cB];
                const uint2 Bl = kfl[cB];
                float d[4] = {0.f, 0.f, 0.f, 0.f};
                mma_bf16(d, Ah0.x, Ah1.x, Ah0.y, Ah1.y, Bh.x, Bh.y);
                mma_bf16(d, Ah0.x, Ah1.x, Ah0.y, Ah1.y, Bl.x, Bl.y);
                mma_bf16(d, Al0.x, Al1.x, Al0.y, Al1.y, Bh.x, Bh.y);
                const float e0 = __expf(d[0]);
                const float e1 = __expf(d[1]);
                const float e2 = __expf(d[2]);
                const float e3 = __expf(d[3]);
                s0 += e0 + e1;
                s1 += e2 + e3;
                ep[kb][0] = packh(e0, e1);   // row q   pair (kt, kt+1)
                ep[kb][1] = packh(e2, e3);   // row q+8
            }
        }
        s0 += __shfl_xor_sync(0xFFFFFFFF, s0, 1);
        s0 += __shfl_xor_sync(0xFFFFFFFF, s0, 2);
        s1 += __shfl_xor_sync(0xFFFFFFFF, s1, 1);
        s1 += __shfl_xor_sync(0xFFFFFFFF, s1, 2);

        // ---- PV (fp16, P single x V 2-term): both 8-col halves ----
        float oA[4] = {0.f, 0.f, 0.f, 0.f};
        float oB[4] = {0.f, 0.f, 0.f, 0.f};
        #pragma unroll
        for (int ks = 0; ks < 4; ++ks) {
            const uint32_t a0 = ep[2 * ks][0], a1 = ep[2 * ks][1];
            const uint32_t a2 = ep[2 * ks + 1][0], a3 = ep[2 * ks + 1][1];
            const int ib = (2 * h) * VST + (2 * ks) * 32 + lane;
            const uint2 c00 = vfp[ib],       c01 = vfp[ib + 32];
            const uint2 c10 = vfp[ib + VST], c11 = vfp[ib + VST + 32];
            mma_f16(oA, a0, a1, a2, a3, c00.x, c01.x);
            mma_f16(oA, a0, a1, a2, a3, c00.y, c01.y);
            mma_f16(oB, a0, a1, a2, a3, c10.x, c11.x);
            mma_f16(oB, a0, a1, a2, a3, c10.y, c11.y);
        }

        // ---- normalize + store O as single-term fp16 out-proj B fragments ----
        const float r0 = 1.f / s0;
        const float r1 = 1.f / s1;
        ofp[cA]       = make_uint2(packh(oA[0] * r0, oA[1] * r0), packh(oB[0] * r0, oB[1] * r0));
        ofp[cA + 256] = make_uint2(packh(oA[2] * r1, oA[3] * r1), packh(oB[2] * r1, oB[3] * r1));
    }
    __syncthreads();

    // ---------- out = Wout @ O + bout : fp16 2-term, 16 warp-tasks ----------
    {
        const int ch    = 6 + (wid >> 3);
        const int wrb   = (wid >> 1) & 3;
        const int nhalf = wid & 1;
        const uint4* ph = gWh + ((ch * 4 + wrb) * 8) * 32 + lane;
        const uint4* pl = gWl + ((ch * 4 + wrb) * 8) * 32 + lane;
        float d[4][4];
        #pragma unroll
        for (int nt = 0; nt < 4; ++nt)
            #pragma unroll
            for (int j = 0; j < 4; ++j) d[nt][j] = 0.f;
        #pragma unroll
        for (int ks = 0; ks < 8; ++ks) {
            const uint4 ah = __ldg(ph + ks * 32);
            const uint4 al = __ldg(pl + ks * 32);
            #pragma unroll
            for (int nt = 0; nt < 4; ++nt) {
                const uint2 bb = ofp[((nhalf * 4 + nt) * 8 + ks) * 32 + lane];
                mma_f16(d[nt], ah.x, ah.y, ah.z, ah.w, bb.x, bb.y);
                mma_f16(d[nt], al.x, al.y, al.z, al.w, bb.x, bb.y);
            }
        }
        const int e0 = (ch - 6) * 64 + wrb * 16 + g;
        const float bb0 = __ldg(bout + e0);
        const float bb1 = __ldg(bout + e0 + 8);
        float* o0 = out + (size_t)b * CDIM * SDIM + (size_t)e0 * SDIM + n * 64 + nhalf * 32 + t4 * 2;
        float* o1 = o0 + (size_t)8 * SDIM;
        #pragma unroll
        for (int nt = 0; nt < 4; ++nt) {
            *reinterpret_cast<float2*>(o0 + nt * 8) = make_float2(d[nt][0] + bb0, d[nt][1] + bb0);
            *reinterpret_cast<float2*>(o1 + nt * 8) = make_float2(d[nt][2] + bb1, d[nt][3] + bb1);
        }
    }
}

extern "C" void kernel_launch(void* const* d_in, const int* in_sizes, int n_in,
                              void* d_out, int out_size)
{
    (void)in_sizes; (void)n_in; (void)out_size;
    const float* x    = (const float*)d_in[0];
    const float* Wqkv = (const float*)d_in[1];
    const float* Wout = (const float*)d_in[2];
    const float* bout = (const float*)d_in[3];
    float* out = (float*)d_out;

    prep_weights<<<32, 256>>>(Wqkv, Wout);

    cudaFuncSetAttribute(lwa3d_mma, cudaFuncAttributeMaxDynamicSharedMemorySize, SMEM_BYTES);
    dim3 grid(NWIN, 2);
    lwa3d_mma<<<grid, 512, SMEM_BYTES>>>(x, bout, out);
}

// round 12
// speedup vs baseline: 1.5942x; 1.0826x over previous
#include <cuda_runtime.h>
#include <cuda_bf16.h>
#include <cuda_fp16.h>
#include <cstdint>

// LocalWindowAttention3D R12: R11 + operand reuse across warp-tasks.
// QKV: 3 chunks per warp share B-frags (ks-outer loop, 3 accum sets).
// Attention: both warp tasks share head h -> K/V frags loaded once.
// bf16 3-term QKV/QK, fp16 PV + out-proj. 512 thr/CTA, 4 syncs.

namespace {
constexpr int CDIM = 128;
constexpr int SDIM = 110592;      // 48^3
constexpr int NWIN = 1728;        // 12^3
constexpr int XP   = 72;          // xs gather pitch (floats)
// ---- smem plan (bytes) ----
constexpr int O_QFH = 0;          // 2048 uint2 = 16384
constexpr int O_QFL = 16384;
constexpr int O_KFH = 32768;
constexpr int O_KFL = 49152;      // -> 65536
constexpr int O_VF  = 65536;      // uint2[16*264] = 33792 -> 99328
constexpr int O_OF  = 99328;      // uint2[2048] = 16384 -> 115712
// aliases (time-disjoint):
constexpr int O_XS  = 65536;      // gather scratch 36864 (dead before vf writes)
constexpr int O_XB  = 102400;     // x frags uint4[2048] = 32768 (dead before of reads)
constexpr int SMEM_BYTES = 135168;
constexpr int VST = 264;          // vf cblk stride in uint2 cells
}

// Weight fragment images: [ch(8)][wrb(4)][ks(8)][lane(32)] uint4.
// ch 0..5 = Wqkv bf16x2 pairs (c0+t4, c0+t4+4), (c0+8+t4, c0+12+t4).
// ch 6..7 = Wout fp16x2 pairs (c0+2t4, +1), (c0+2t4+8, +9).
__device__ uint4 gWh[8 * 4 * 8 * 32];
__device__ uint4 gWl[8 * 4 * 8 * 32];

__device__ __forceinline__ void split2(float a, float b, uint32_t& hi, uint32_t& lo) {
    __nv_bfloat162 h = __floats2bfloat162_rn(a, b);
    const float ra = a - __low2float(h);
    const float rb = b - __high2float(h);
    __nv_bfloat162 l = __floats2bfloat162_rn(ra, rb);
    hi = *reinterpret_cast<uint32_t*>(&h);
    lo = *reinterpret_cast<uint32_t*>(&l);
}
__device__ __forceinline__ void split2h(float a, float b, uint32_t& hi, uint32_t& lo) {
    __half2 h = __floats2half2_rn(a, b);
    const float ra = a - __half2float(__low2half(h));
    const float rb = b - __half2float(__high2half(h));
    __half2 l = __floats2half2_rn(ra, rb);
    hi = *reinterpret_cast<uint32_t*>(&h);
    lo = *reinterpret_cast<uint32_t*>(&l);
}
__device__ __forceinline__ uint32_t packh(float a, float b) {
    __half2 h = __floats2half2_rn(a, b);
    return *reinterpret_cast<uint32_t*>(&h);
}
__device__ __forceinline__ void mma_bf16(float* d, uint32_t a0, uint32_t a1, uint32_t a2,
                                         uint32_t a3, uint32_t b0, uint32_t b1) {
    asm volatile(
        "mma.sync.aligned.m16n8k16.row.col.f32.bf16.bf16.f32 "
        "{%0,%1,%2,%3}, {%4,%5,%6,%7}, {%8,%9}, {%0,%1,%2,%3};"
        : "+f"(d[0]), "+f"(d[1]), "+f"(d[2]), "+f"(d[3])
        : "r"(a0), "r"(a1), "r"(a2), "r"(a3), "r"(b0), "r"(b1));
}
__device__ __forceinline__ void mma_f16(float* d, uint32_t a0, uint32_t a1, uint32_t a2,
                                        uint32_t a3, uint32_t b0, uint32_t b1) {
    asm volatile(
        "mma.sync.aligned.m16n8k16.row.col.f32.f16.f16.f32 "
        "{%0,%1,%2,%3}, {%4,%5,%6,%7}, {%8,%9}, {%0,%1,%2,%3};"
        : "+f"(d[0]), "+f"(d[1]), "+f"(d[2]), "+f"(d[3])
        : "r"(a0), "r"(a1), "r"(a2), "r"(a3), "r"(b0), "r"(b1));
}

__global__ void prep_weights(const float* __restrict__ Wqkv, const float* __restrict__ Wout) {
    const int idx = blockIdx.x * 256 + threadIdx.x;     // 8192 frags
    if (idx >= 8192) return;
    const int lane = idx & 31;
    const int ks   = (idx >> 5) & 7;
    const int wrb  = (idx >> 8) & 3;
    const int ch   = idx >> 10;
    const int g = lane >> 2, t4 = lane & 3;
    const int e0 = ch * 64 + wrb * 16 + g;
    const float* W0 = (ch < 6) ? (Wqkv + (size_t)e0 * CDIM) : (Wout + (size_t)(e0 - 384) * CDIM);
    const float* W8 = W0 + 8 * CDIM;
    const int c0 = ks * 16;
    uint4 h, l;
    if (ch < 6) {
        const int cs0 = c0 + t4, cs1 = c0 + t4 + 4, cs2 = c0 + 8 + t4, cs3 = c0 + 12 + t4;
        split2(W0[cs0], W0[cs1], h.x, l.x);
        split2(W8[cs0], W8[cs1], h.y, l.y);
        split2(W0[cs2], W0[cs3], h.z, l.z);
        split2(W8[cs2], W8[cs3], h.w, l.w);
    } else {
        const int cs0 = c0 + t4 * 2, cs1 = cs0 + 1, cs2 = cs0 + 8, cs3 = cs0 + 9;
        split2h(W0[cs0], W0[cs1], h.x, l.x);
        split2h(W8[cs0], W8[cs1], h.y, l.y);
        split2h(W0[cs2], W0[cs3], h.z, l.z);
        split2h(W8[cs2], W8[cs3], h.w, l.w);
    }
    gWh[idx] = h;
    gWl[idx] = l;
}

__global__ __launch_bounds__(512, 1)
void lwa3d_mma(const float* __restrict__ x, const float* __restrict__ bout,
               float* __restrict__ out)
{
    extern __shared__ char smc[];
    uint2* qfh = reinterpret_cast<uint2*>(smc + O_QFH);
    uint2* qfl = reinterpret_cast<uint2*>(smc + O_QFL);
    uint2* kfh = reinterpret_cast<uint2*>(smc + O_KFH);
    uint2* kfl = reinterpret_cast<uint2*>(smc + O_KFL);
    uint32_t* qfhw = reinterpret_cast<uint32_t*>(smc + O_QFH);
    uint32_t* qflw = reinterpret_cast<uint32_t*>(smc + O_QFL);
    uint32_t* kfhw = reinterpret_cast<uint32_t*>(smc + O_KFH);
    uint32_t* kflw = reinterpret_cast<uint32_t*>(smc + O_KFL);
    uint2* vfp = reinterpret_cast<uint2*>(smc + O_VF);
    uint2* ofp = reinterpret_cast<uint2*>(smc + O_OF);
    float* xs  = reinterpret_cast<float*>(smc + O_XS);
    uint4* xbp = reinterpret_cast<uint4*>(smc + O_XB);

    const int tid  = threadIdx.x;
    const int wid  = tid >> 5;
    const int lane = tid & 31;
    const int g    = lane >> 2;
    const int t4   = lane & 3;
    const int n = blockIdx.x;
    const int b = blockIdx.y;
    const float scale = 0.08838834764831845f;   // 128^-0.5

    // ---------- gather x window into xs [128c][64t] ----------
    {
        const int ndi = n / 144, nhi = (n / 12) % 12, nwi = n % 12;
        const float* xb = x + (size_t)b * CDIM * SDIM;
        const int sbase = ((ndi * 4) * 48 + nhi * 4) * 48 + nwi * 4;
        for (int i = tid; i < CDIM * 16; i += 512) {
            const int c = i >> 4;
            const int gg = i & 15;
            const int s0 = sbase + ((gg >> 2) * 48 + (gg & 3)) * 48;
            *reinterpret_cast<float4*>(xs + c * XP + gg * 4) =
                *reinterpret_cast<const float4*>(xb + (size_t)c * SDIM + s0);
        }
    }
    __syncthreads();

    // ---------- build packed bf16 hi/lo x B-fragments ----------
    for (int cell = tid; cell < 2048; cell += 512) {
        const int l2 = cell & 31;
        const int ks = (cell >> 5) & 7;
        const int tb = cell >> 8;
        const int t  = tb * 8 + (l2 >> 2);
        const int c0 = ks * 16 + (l2 & 3);
        uint32_t h0, l0, h1, l1;
        split2(xs[c0 * XP + t], xs[(c0 + 4) * XP + t], h0, l0);
        split2(xs[(c0 + 8) * XP + t], xs[(c0 + 12) * XP + t], h1, l1);
        xbp[cell] = make_uint4(h0, h1, l0, l1);
    }
    __syncthreads();

    // ---------- QKV = Wqkv @ x : 3 chunks/warp sharing B (ks-outer) ----------
    {
        const int nhalf = wid & 1;
        const int p0 = (wid >> 1) * 3;          // 3 (ch,wrb) pairs per warp
        const uint4* ph[3];
        const uint4* pl[3];
        #pragma unroll
        for (int i = 0; i < 3; ++i) {
            const int p = p0 + i;
            const int cw = (p >> 2) * 4 + (p & 3);      // ch*4+wrb
            ph[i] = gWh + (cw * 8) * 32 + lane;
            pl[i] = gWl + (cw * 8) * 32 + lane;
        }
        float d[3][4][4];
        #pragma unroll
        for (int i = 0; i < 3; ++i)
            #pragma unroll
            for (int nt = 0; nt < 4; ++nt)
                #pragma unroll
                for (int j = 0; j < 4; ++j) d[i][nt][j] = 0.f;

        #pragma unroll
        for (int ks = 0; ks < 8; ++ks) {
            uint4 bb[4];
            #pragma unroll
            for (int nt = 0; nt < 4; ++nt)
                bb[nt] = xbp[((nhalf * 4 + nt) * 8 + ks) * 32 + lane];
            #pragma unroll
            for (int i = 0; i < 3; ++i) {
                const uint4 ah = __ldg(ph[i] + ks * 32);
                const uint4 al = __ldg(pl[i] + ks * 32);
                #pragma unroll
                for (int nt = 0; nt < 4; ++nt) {
                    mma_bf16(d[i][nt], ah.x, ah.y, ah.z, ah.w, bb[nt].x, bb[nt].y);
                    mma_bf16(d[i][nt], ah.x, ah.y, ah.z, ah.w, bb[nt].z, bb[nt].w);
                    mma_bf16(d[i][nt], al.x, al.y, al.z, al.w, bb[nt].x, bb[nt].y);
                }
            }
        }

        // epilogues (identical maps to R11)
        #pragma unroll
        for (int i = 0; i < 3; ++i) {
            const int p = p0 + i;
            const int ch  = p >> 2;
            const int wrb = p & 3;
            if (ch < 4) {
                const int h = (ch & 1) * 4 + wrb;
                uint32_t* fh = (ch < 2) ? qfhw : kfhw;
                uint32_t* fl = (ch < 2) ? qflw : kflw;
                const float sc = (ch < 2) ? scale : 1.f;
                #pragma unroll
                for (int nt = 0; nt < 4; ++nt) {
                    const int tb = nhalf * 4 + nt;
                    uint32_t hh0, ll0, hh1, ll1;
                    split2(d[i][nt][0] * sc, d[i][nt][2] * sc, hh0, ll0);
                    split2(d[i][nt][1] * sc, d[i][nt][3] * sc, hh1, ll1);
                    const int base = (tb * 8 + h) * 32 + (g & 3);
                    const int i0 = ((base + (2 * t4) * 4) << 1) | (g >> 2);
                    const int i1 = ((base + (2 * t4 + 1) * 4) << 1) | (g >> 2);
                    fh[i0] = hh0; fl[i0] = ll0;
                    fh[i1] = hh1; fl[i1] = ll1;
                }
            } else {
                const int cb0 = (ch & 1) * 8 + wrb * 2;
                const int lane2 = g * 4 + t4;
                #pragma unroll
                for (int nt = 0; nt < 4; ++nt) {
                    const int kb = nhalf * 4 + nt;
                    uint32_t h0, l0, h1, l1;
                    split2h(d[i][nt][0], d[i][nt][1], h0, l0);
                    split2h(d[i][nt][2], d[i][nt][3], h1, l1);
                    vfp[cb0 * VST + kb * 32 + lane2] = make_uint2(h0, l0);
                    vfp[(cb0 + 1) * VST + kb * 32 + lane2] = make_uint2(h1, l1);
                }
            }
        }
    }
    __syncthreads();

    // ---------- attention: warp owns head h = wid>>1, q-blocks mb0, mb0+1 ----------
    {
        const int h   = wid >> 1;
        const int mb0 = (wid & 1) * 2;

        const int cA0 = (2 * mb0 * 8 + h) * 32 + lane;
        const int cA1 = (2 * (mb0 + 1) * 8 + h) * 32 + lane;
        const uint2 A0h0 = qfh[cA0], A0h1 = qfh[cA0 + 256];
        const uint2 A0l0 = qfl[cA0], A0l1 = qfl[cA0 + 256];
        const uint2 A1h0 = qfh[cA1], A1h1 = qfh[cA1 + 256];
        const uint2 A1l0 = qfl[cA1], A1l1 = qfl[cA1 + 256];

        uint32_t ep0[8][2], ep1[8][2];
        float s00 = 0.f, s01 = 0.f, s10 = 0.f, s11 = 0.f;
        #pragma unroll
        for (int kb = 0; kb < 8; ++kb) {
            const int cB = (kb * 8 + h) * 32 + lane;
            const uint2 Bh = kfh[cB];
            const uint2 Bl = kfl[cB];
            float d0[4] = {0.f, 0.f, 0.f, 0.f};
            float d1[4] = {0.f, 0.f, 0.f, 0.f};
            mma_bf16(d0, A0h0.x, A0h1.x, A0h0.y, A0h1.y, Bh.x, Bh.y);
            mma_bf16(d0, A0h0.x, A0h1.x, A0h0.y, A0h1.y, Bl.x, Bl.y);
            mma_bf16(d0, A0l0.x, A0l1.x, A0l0.y, A0l1.y, Bh.x, Bh.y);
            mma_bf16(d1, A1h0.x, A1h1.x, A1h0.y, A1h1.y, Bh.x, Bh.y);
            mma_bf16(d1, A1h0.x, A1h1.x, A1h0.y, A1h1.y, Bl.x, Bl.y);
            mma_bf16(d1, A1l0.x, A1l1.x, A1l0.y, A1l1.y, Bh.x, Bh.y);
            const float e00 = __expf(d0[0]);
            const float e01 = __expf(d0[1]);
            const float e02 = __expf(d0[2]);
            const float e03 = __expf(d0[3]);
            s00 += e00 + e01;
            s01 += e02 + e03;
            ep0[kb][0] = packh(e00, e01);
            ep0[kb][1] = packh(e02, e03);
            const float e10 = __expf(d1[0]);
            const float e11 = __expf(d1[1]);
            const float e12 = __expf(d1[2]);
            const float e13 = __expf(d1[3]);
            s10 += e10 + e11;
            s11 += e12 + e13;
            ep1[kb][0] = packh(e10, e11);
            ep1[kb][1] = packh(e12, e13);
        }
        s00 += __shfl_xor_sync(0xFFFFFFFF, s00, 1);
        s00 += __shfl_xor_sync(0xFFFFFFFF, s00, 2);
        s01 += __shfl_xor_sync(0xFFFFFFFF, s01, 1);
        s01 += __shfl_xor_sync(0xFFFFFFFF, s01, 2);
        s10 += __shfl_xor_sync(0xFFFFFFFF, s10, 1);
        s10 += __shfl_xor_sync(0xFFFFFFFF, s10, 2);
        s11 += __shfl_xor_sync(0xFFFFFFFF, s11, 1);
        s11 += __shfl_xor_sync(0xFFFFFFFF, s11, 2);

        // ---- PV (fp16): V frags loaded once, used by both q-blocks ----
        float oA0[4] = {0.f, 0.f, 0.f, 0.f};
        float oB0[4] = {0.f, 0.f, 0.f, 0.f};
        float oA1[4] = {0.f, 0.f, 0.f, 0.f};
        float oB1[4] = {0.f, 0.f, 0.f, 0.f};
        #pragma unroll
        for (int ks = 0; ks < 4; ++ks) {
            const int ib = (2 * h) * VST + (2 * ks) * 32 + lane;
            const uint2 c00 = vfp[ib],       c01 = vfp[ib + 32];
            const uint2 c10 = vfp[ib + VST], c11 = vfp[ib + VST + 32];
            const uint32_t a00 = ep0[2 * ks][0], a01 = ep0[2 * ks][1];
            const uint32_t a02 = ep0[2 * ks + 1][0], a03 = ep0[2 * ks + 1][1];
            const uint32_t a10 = ep1[2 * ks][0], a11 = ep1[2 * ks][1];
            const uint32_t a12 = ep1[2 * ks + 1][0], a13 = ep1[2 * ks + 1][1];
            mma_f16(oA0, a00, a01, a02, a03, c00.x, c01.x);
            mma_f16(oA0, a00, a01, a02, a03, c00.y, c01.y);
            mma_f16(oB0, a00, a01, a02, a03, c10.x, c11.x);
            mma_f16(oB0, a00, a01, a02, a03, c10.y, c11.y);
            mma_f16(oA1, a10, a11, a12, a13, c00.x, c01.x);
            mma_f16(oA1, a10, a11, a12, a13, c00.y, c01.y);
            mma_f16(oB1, a10, a11, a12, a13, c10.x, c11.x);
            mma_f16(oB1, a10, a11, a12, a13, c10.y, c11.y);
        }

        // ---- normalize + store O (single fp16) as out-proj B fragments ----
        {
            const float r0 = 1.f / s00;
            const float r1 = 1.f / s01;
            ofp[cA0]       = make_uint2(packh(oA0[0] * r0, oA0[1] * r0),
                                        packh(oB0[0] * r0, oB0[1] * r0));
            ofp[cA0 + 256] = make_uint2(packh(oA0[2] * r1, oA0[3] * r1),
                                        packh(oB0[2] * r1, oB0[3] * r1));
        }
        {
            const float r0 = 1.f / s10;
            const float r1 = 1.f / s11;
            ofp[cA1]       = make_uint2(packh(oA1[0] * r0, oA1[1] * r0),
                                        packh(oB1[0] * r0, oB1[1] * r0));
            ofp[cA1 + 256] = make_uint2(packh(oA1[2] * r1, oA1[3] * r1),
                                        packh(oB1[2] * r1, oB1[3] * r1));
        }
    }
    __syncthreads();

    // ---------- out = Wout @ O + bout : fp16 2-term, 16 warp-tasks ----------
    {
        const int ch    = 6 + (wid >> 3);
        const int wrb   = (wid >> 1) & 3;
        const int nhalf = wid & 1;
        const uint4* ph = gWh + ((ch * 4 + wrb) * 8) * 32 + lane;
        const uint4* pl = gWl + ((ch * 4 + wrb) * 8) * 32 + lane;
        float d[4][4];
        #pragma unroll
        for (int nt = 0; nt < 4; ++nt)
            #pragma unroll
            for (int j = 0; j < 4; ++j) d[nt][j] = 0.f;
        #pragma unroll
        for (int ks = 0; ks < 8; ++ks) {
            const uint4 ah = __ldg(ph + ks * 32);
            const uint4 al = __ldg(pl + ks * 32);
            #pragma unroll
            for (int nt = 0; nt < 4; ++nt) {
                const uint2 bb = ofp[((nhalf * 4 + nt) * 8 + ks) * 32 + lane];
                mma_f16(d[nt], ah.x, ah.y, ah.z, ah.w, bb.x, bb.y);
                mma_f16(d[nt], al.x, al.y, al.z, al.w, bb.x, bb.y);
            }
        }
        const int e0 = (ch - 6) * 64 + wrb * 16 + g;
        const float bb0 = __ldg(bout + e0);
        const float bb1 = __ldg(bout + e0 + 8);
        float* o0 = out + (size_t)b * CDIM * SDIM + (size_t)e0 * SDIM + n * 64 + nhalf * 32 + t4 * 2;
        float* o1 = o0 + (size_t)8 * SDIM;
        #pragma unroll
        for (int nt = 0; nt < 4; ++nt) {
            *reinterpret_cast<float2*>(o0 + nt * 8) = make_float2(d[nt][0] + bb0, d[nt][1] + bb0);
            *reinterpret_cast<float2*>(o1 + nt * 8) = make_float2(d[nt][2] + bb1, d[nt][3] + bb1);
        }
    }
}

extern "C" void kernel_launch(void* const* d_in, const int* in_sizes, int n_in,
                              void* d_out, int out_size)
{
    (void)in_sizes; (void)n_in; (void)out_size;
    const float* x    = (const float*)d_in[0];
    const float* Wqkv = (const float*)d_in[1];
    const float* Wout = (const float*)d_in[2];
    const float* bout = (const float*)d_in[3];
    float* out = (float*)d_out;

    prep_weights<<<32, 256>>>(Wqkv, Wout);

    cudaFuncSetAttribute(lwa3d_mma, cudaFuncAttributeMaxDynamicSharedMemorySize, SMEM_BYTES);
    dim3 grid(NWIN, 2);
    lwa3d_mma<<<grid, 512, SMEM_BYTES>>>(x, bout, out);
}